// round 3
// baseline (speedup 1.0000x reference)
#include <cuda_runtime.h>
#include <cstdint>

// ---- problem constants (match reference) ----
#define BB 4
#define HH 128
#define WW 128
#define SS 72
#define SPS 24          // slices per stack
#define ZS 120          // z_scale
#define ZV 122          // padded depth
#define ST_RATIO 5.0f

#define VOXELS (BB * HH * WW * ZV)      // 7,995,392
#define PIXELS (BB * HH * WW * SS)      // 4,718,592
#define OUT_PER (BB * HH * WW * ZS)     // 7,864,320

// Interleaved scratch: [2*lin] = N accumulator, [2*lin+1] = D accumulator.
// 8-byte aligned pairs -> one red.global.add.v2.f32 per corner.
__device__ __align__(16) float g_acc[2 * VOXELS];     // ~64 MB, fits in L2

__device__ __forceinline__ void red_add_v2(float* p, float a, float b) {
    // vector reduction (sm_90+): adds {a,b} to the 8B-aligned pair at p
    asm volatile("red.global.add.v2.f32 [%0], {%1, %2};"
                 :: "l"(p), "f"(a), "f"(b) : "memory");
}

// ---------------------------------------------------------------------------
// Splat kernel: one thread per (b,h,w,s) pixel, s fastest (coalesced vol read).
// ---------------------------------------------------------------------------
__global__ __launch_bounds__(256) void splat_kernel(
    const float* __restrict__ vol,   // (B,H,W,S,1) — linear index == thread index
    const float* __restrict__ trf)   // (B,S,3,4)
{
    int i = blockIdx.x * blockDim.x + threadIdx.x;
    if (i >= PIXELS) return;

    int s = i % SS;
    int rem = i / SS;
    int w = rem % WW;
    rem /= WW;
    int h = rem % HH;
    int b = rem / HH;

    float v = vol[i];

    const float* Ap = trf + (size_t)(b * SS + s) * 12;
    // A = trf + eye(4)[:3,:]
    float A00 = Ap[0] + 1.0f, A01 = Ap[1],        A02 = Ap[2],         A03 = Ap[3];
    float A10 = Ap[4],        A11 = Ap[5] + 1.0f, A12 = Ap[6],         A13 = Ap[7];
    float A20 = Ap[8],        A21 = Ap[9],        A22 = Ap[10] + 1.0f, A23 = Ap[11];

    int o = s / SPS;                       // 0=axi, 1=cor, 2=sag
    float t = (float)(s % SPS) * ST_RATIO;

    float bx, by, bz;
    if (o == 0)      { bx = (float)h; by = (float)w; bz = t; }
    else if (o == 1) { bx = (float)h; by = t;        bz = (float)w; }
    else             { bx = t;        by = (float)h; bz = (float)w; }

    float x = A00 * bx + A01 * by + A02 * bz + A03;
    float y = A10 * bx + A11 * by + A12 * bz + A13;
    float z = A20 * bx + A21 * by + A22 * bz + A23 + 1.0f;   // +1 pad offset

    float x0f = floorf(x), y0f = floorf(y), z0f = floorf(z);
    float wx = x - x0f, wy = y - y0f, wz = z - z0f;
    int x0 = (int)x0f, y0 = (int)y0f, z0 = (int)z0f;

    int base_b = b * HH;

    #pragma unroll
    for (int dx = 0; dx < 2; dx++) {
        int xi = x0 + dx;
        if (xi < 0 || xi >= HH) continue;
        float fwx = dx ? wx : (1.0f - wx);
        #pragma unroll
        for (int dy = 0; dy < 2; dy++) {
            int yi = y0 + dy;
            if (yi < 0 || yi >= WW) continue;
            float fwy = dy ? wy : (1.0f - wy);
            float fwxy = fwx * fwy;
            int lin_xy = ((base_b + xi) * WW + yi) * ZV;
            #pragma unroll
            for (int dz = 0; dz < 2; dz++) {
                int zi = z0 + dz;
                if (zi < 0 || zi >= ZV) continue;
                float ww = fwxy * (dz ? wz : (1.0f - wz));
                int lin = lin_xy + zi;
                red_add_v2(&g_acc[2 * lin], ww * v, ww);
            }
        }
    }
}

// ---------------------------------------------------------------------------
// Finalize: crop z[1:1+ZS], split interleaved N/D, apply where(D<=0, 1, D).
// Output layout: N block (B,H,W,ZS) then D block (B,H,W,ZS).
// ---------------------------------------------------------------------------
__global__ __launch_bounds__(256) void finalize_kernel(float* __restrict__ out)
{
    int j = blockIdx.x * blockDim.x + threadIdx.x;
    if (j >= OUT_PER) return;

    int z = j % ZS;
    int hwb = j / ZS;                 // (b*H+h)*W + w
    int lin = hwb * ZV + (z + 1);

    float2 nd = *reinterpret_cast<const float2*>(&g_acc[2 * lin]);

    out[j]           = nd.x;
    out[OUT_PER + j] = (nd.y > 0.0f) ? nd.y : 1.0f;
}

// ---------------------------------------------------------------------------
extern "C" void kernel_launch(void* const* d_in, const int* in_sizes, int n_in,
                              void* d_out, int out_size)
{
    const float* vol = (const float*)d_in[0];
    const float* trf = (const float*)d_in[1];
    float* out = (float*)d_out;

    void* acc_ptr = nullptr;
    cudaGetSymbolAddress(&acc_ptr, g_acc);
    cudaMemsetAsync(acc_ptr, 0, sizeof(float) * 2 * VOXELS, 0);

    {
        int threads = 256;
        int blocks = (PIXELS + threads - 1) / threads;
        splat_kernel<<<blocks, threads>>>(vol, trf);
    }
    {
        int threads = 256;
        int blocks = (OUT_PER + threads - 1) / threads;
        finalize_kernel<<<blocks, threads>>>(out);
    }
}

// round 4
// speedup vs baseline: 1.6774x; 1.6774x over previous
#include <cuda_runtime.h>
#include <cstdint>

// ---- problem constants (match reference) ----
#define BB 4
#define HH 128
#define WW 128
#define SS 72
#define SPS 24          // slices per stack
#define ZS 120          // z_scale
#define ZV 122          // padded depth
#define ST_RATIO 5.0f

#define VOXELS (BB * HH * WW * ZV)      // 7,995,392
#define PIXELS (BB * HH * WW * SS)      // 4,718,592
#define OUT_PER (BB * HH * WW * ZS)     // 7,864,320
#define HWSZ   (HH * WW)                // 16384

// Interleaved scratch: [2*lin]=N, [2*lin+1]=D. 64 MB, L2-resident.
__device__ __align__(16) float g_acc[2 * VOXELS];
// vol transposed to (b, s, h, w) so the splat's lane->w mapping reads coalesced.
__device__ __align__(16) float g_volT[PIXELS];

__device__ __forceinline__ void red_add_v2(float* p, float a, float b) {
    asm volatile("red.global.add.v2.f32 [%0], {%1, %2};"
                 :: "l"(p), "f"(a), "f"(b) : "memory");
}

// ---------------------------------------------------------------------------
// Transpose (b,h,w,s) -> (b,s,h,w). Coalesced both sides via smem tile.
// Block = 256 threads handles 32 consecutive hw values x all 72 s (contiguous
// 9216B source chunk). Grid = B * (HW/32) = 2048 blocks.
// ---------------------------------------------------------------------------
__global__ __launch_bounds__(256) void transpose_kernel(const float* __restrict__ vol)
{
    __shared__ float tile[32 * 73];
    int blk = blockIdx.x;
    int b   = blk >> 9;             // / 512
    int hw0 = (blk & 511) << 5;     // * 32

    const float* src = vol + ((size_t)b * HWSZ + hw0) * SS;
    #pragma unroll
    for (int t = threadIdx.x; t < 32 * SS; t += 256) {
        int l = t / SS, s = t - l * SS;
        tile[l * 73 + s] = src[t];               // coalesced read
    }
    __syncthreads();
    float* dst = g_volT + (size_t)b * SS * HWSZ;
    #pragma unroll
    for (int t = threadIdx.x; t < 32 * SS; t += 256) {
        int s = t >> 5, l = t & 31;
        dst[(size_t)s * HWSZ + hw0 + l] = tile[l * 73 + s];  // coalesced write
    }
}

// ---------------------------------------------------------------------------
// Merged-pair emit along the warp-varying merge axis.
// lo_lin/hi_lin: clipped voxel linear indices of the low/high corner.
// wlo/whi: fully masked weights (0 if that corner is out of bounds).
// Lane l absorbs lane l-1's high-corner contribution iff the addresses are
// exactly equal (sum-preserving regardless of clipping). All lanes converged.
// ---------------------------------------------------------------------------
__device__ __forceinline__ void emit_pair(int lane, int lo_lin, int hi_lin,
                                          float wlo, float whi, float v)
{
    float Nhi = whi * v;
    float nbN = __shfl_up_sync(0xffffffffu, Nhi, 1);
    float nbD = __shfl_up_sync(0xffffffffu, whi, 1);
    int   nbL = __shfl_up_sync(0xffffffffu, hi_lin, 1);

    bool mrg = (lane > 0) && (nbL == lo_lin);
    unsigned bal = __ballot_sync(0xffffffffu, mrg);
    bool absorbed = (bal & (2u << lane)) != 0u;   // lane 31: 2u<<31 == 0 -> false

    float addN = mrg ? nbN : 0.0f;
    float addD = mrg ? nbD : 0.0f;

    red_add_v2(&g_acc[2 * lo_lin], wlo * v + addN, wlo + addD);
    if (!absorbed)
        red_add_v2(&g_acc[2 * hi_lin], Nhi, whi);
}

// ---------------------------------------------------------------------------
// Splat: warp lanes span w; (b,h,s) warp-uniform (=> orientation warp-uniform).
// Block = 8 warps covering 8 consecutive slices for the same (b,h,w-chunk).
// Grid = B * 9 * H * 4 = 18432 blocks of 256.
// ---------------------------------------------------------------------------
__global__ __launch_bounds__(256) void splat_kernel(const float* __restrict__ trf)
{
    int lane = threadIdx.x & 31;
    int wid  = threadIdx.x >> 5;
    int blk  = blockIdx.x;

    int wc = blk & 3;                 // w chunk (0..3)
    int h  = (blk >> 2) & 127;
    int sc = (blk >> 9) % 9;          // s chunk (0..8)
    int b  = blk / 4608;

    int s = sc * 8 + wid;             // warp-uniform
    int w = wc * 32 + lane;

    float v = g_volT[(((size_t)b * SS + s) * HH + h) * WW + w];  // coalesced

    const float* Ap = trf + (size_t)(b * SS + s) * 12;
    float A00 = Ap[0] + 1.0f, A01 = Ap[1],        A02 = Ap[2],         A03 = Ap[3];
    float A10 = Ap[4],        A11 = Ap[5] + 1.0f, A12 = Ap[6],         A13 = Ap[7];
    float A20 = Ap[8],        A21 = Ap[9],        A22 = Ap[10] + 1.0f, A23 = Ap[11];

    int o = s / SPS;                  // 0=axi, 1=cor, 2=sag  (warp-uniform)
    float t = (float)(s % SPS) * ST_RATIO;

    float bx, by, bz;
    if (o == 0)      { bx = (float)h; by = (float)w; bz = t; }
    else if (o == 1) { bx = (float)h; by = t;        bz = (float)w; }
    else             { bx = t;        by = (float)h; bz = (float)w; }

    float x = A00 * bx + A01 * by + A02 * bz + A03;
    float y = A10 * bx + A11 * by + A12 * bz + A13;
    float z = A20 * bx + A21 * by + A22 * bz + A23 + 1.0f;

    float x0f = floorf(x), y0f = floorf(y), z0f = floorf(z);
    float wx = x - x0f, wy = y - y0f, wz = z - z0f;
    int x0 = (int)x0f, y0 = (int)y0f, z0 = (int)z0f;

    // clipped indices + validity masks (as weights)
    int cx0 = min(max(x0,     0), HH - 1);
    int cx1 = min(max(x0 + 1, 0), HH - 1);
    int cy0 = min(max(y0,     0), WW - 1);
    int cy1 = min(max(y0 + 1, 0), WW - 1);
    int cz0 = min(max(z0,     0), ZV - 1);
    int cz1 = min(max(z0 + 1, 0), ZV - 1);
    float vx0 = (x0 >= 0 && x0 < HH)         ? 1.0f : 0.0f;
    float vx1 = (x0 + 1 >= 0 && x0 + 1 < HH) ? 1.0f : 0.0f;
    float vy0 = (y0 >= 0 && y0 < WW)         ? 1.0f : 0.0f;
    float vy1 = (y0 + 1 >= 0 && y0 + 1 < WW) ? 1.0f : 0.0f;
    float vz0 = (z0 >= 0 && z0 < ZV)         ? 1.0f : 0.0f;
    float vz1 = (z0 + 1 >= 0 && z0 + 1 < ZV) ? 1.0f : 0.0f;

    float fx0 = (1.0f - wx) * vx0, fx1 = wx * vx1;
    float fy0 = (1.0f - wy) * vy0, fy1 = wy * vy1;
    float fz0 = (1.0f - wz) * vz0, fz1 = wz * vz1;

    int base_b = b * HH;

    if (o == 0) {
        // axi: y varies with lane -> merge along y (address delta = ZV per y step)
        #pragma unroll
        for (int dx = 0; dx < 2; dx++) {
            int   cx  = dx ? cx1 : cx0;
            float fxm = dx ? fx1 : fx0;
            int row = (base_b + cx) * WW;
            #pragma unroll
            for (int dz = 0; dz < 2; dz++) {
                int   cz  = dz ? cz1 : cz0;
                float fxz = fxm * (dz ? fz1 : fz0);
                int lo_lin = (row + cy0) * ZV + cz;
                int hi_lin = (row + cy1) * ZV + cz;
                emit_pair(lane, lo_lin, hi_lin, fxz * fy0, fxz * fy1, v);
            }
        }
    } else {
        // cor/sag: z varies with lane -> merge along z (address delta = 1)
        #pragma unroll
        for (int dx = 0; dx < 2; dx++) {
            int   cx  = dx ? cx1 : cx0;
            float fxm = dx ? fx1 : fx0;
            int row = (base_b + cx) * WW;
            #pragma unroll
            for (int dy = 0; dy < 2; dy++) {
                int   cy  = dy ? cy1 : cy0;
                float fxy = fxm * (dy ? fy1 : fy0);
                int lin_xy = (row + cy) * ZV;
                emit_pair(lane, lin_xy + cz0, lin_xy + cz1, fxy * fz0, fxy * fz1, v);
            }
        }
    }
}

// ---------------------------------------------------------------------------
// Finalize: crop z[1:1+ZS], split interleaved N/D, where(D<=0, 1, D).
// ---------------------------------------------------------------------------
__global__ __launch_bounds__(256) void finalize_kernel(float* __restrict__ out)
{
    int j = blockIdx.x * blockDim.x + threadIdx.x;
    if (j >= OUT_PER) return;

    int z = j % ZS;
    int hwb = j / ZS;
    int lin = hwb * ZV + (z + 1);

    float2 nd = *reinterpret_cast<const float2*>(&g_acc[2 * lin]);

    out[j]           = nd.x;
    out[OUT_PER + j] = (nd.y > 0.0f) ? nd.y : 1.0f;
}

// ---------------------------------------------------------------------------
extern "C" void kernel_launch(void* const* d_in, const int* in_sizes, int n_in,
                              void* d_out, int out_size)
{
    const float* vol = (const float*)d_in[0];
    const float* trf = (const float*)d_in[1];
    float* out = (float*)d_out;

    void* acc_ptr = nullptr;
    cudaGetSymbolAddress(&acc_ptr, g_acc);
    cudaMemsetAsync(acc_ptr, 0, sizeof(float) * 2 * VOXELS, 0);

    transpose_kernel<<<BB * (HWSZ / 32), 256>>>(vol);
    splat_kernel<<<BB * 9 * HH * 4, 256>>>(trf);
    finalize_kernel<<<(OUT_PER + 255) / 256, 256>>>(out);
}